// round 10
// baseline (speedup 1.0000x reference)
#include <cuda_runtime.h>
#include <cuda_bf16.h>
#include <stdint.h>

#define N_NODES 100000
#define N_EDGES 1600000
#define IN_DIM  128
#define HID_DIM 64
#define OUT_DIM 64

// packed fp32x2 FMA (Blackwell PTX, plain sm_100 feature): d = a*b + d, lanewise
#define FMA2(d, a, b) \
    asm("fma.rn.f32x2 %0, %1, %2, %0;" : "+l"(d) : "l"(a), "l"(b))
#define UNPACK2(lo, hi, d) \
    asm("mov.b64 {%0, %1}, %2;" : "=f"(lo), "=f"(hi) : "l"(d))

// ---------------- scratch (static device globals; no allocation) -------------
__device__ __align__(16) float g_h[N_NODES * 64];   // GEMM output, pre-scaled by dinv (h~)
__device__ __align__(16) float g_a[N_NODES * 64];   // layer1 activations
__device__ __align__(16) int   g_cnt[N_NODES];      // real in-degree (no self-loop)
__device__ __align__(16) int   g_cur[N_NODES];      // fill cursor (seeded to bucket start)
__device__ __align__(16) float g_dinv[N_NODES];     // rsqrt(deg+1)
__device__ __align__(16) int   g_off[N_NODES];      // bucket start (for agg)
__device__ __align__(16) int   g_src[N_EDGES];      // source id only
__device__ int g_total;                             // global bucket cursor

// ---------------- init: zero g_cnt (int4-vectorized) -------------------------
__global__ void init_kernel() {
    int i = blockIdx.x * blockDim.x + threadIdx.x;
    int j = i * 4;
    if (j + 3 < N_NODES) {
        *(int4*)(g_cnt + j) = make_int4(0, 0, 0, 0);
    } else if (j < N_NODES) {
        for (int t = j; t < N_NODES; t++) g_cnt[t] = 0;
    }
    if (i == 0) g_total = 0;
}

// ---------------- degree histogram (edge_index int32 [2, N_EDGES]) -----------
__global__ void hist_kernel(const int* __restrict__ eidx) {
    int e0 = (blockIdx.x * blockDim.x + threadIdx.x) * 4;
    if (e0 < N_EDGES) {
        int4 d4 = *(const int4*)(eidx + N_EDGES + e0);
        if ((unsigned)d4.x < (unsigned)N_NODES) atomicAdd(&g_cnt[d4.x], 1);
        if ((unsigned)d4.y < (unsigned)N_NODES) atomicAdd(&g_cnt[d4.y], 1);
        if ((unsigned)d4.z < (unsigned)N_NODES) atomicAdd(&g_cnt[d4.z], 1);
        if ((unsigned)d4.w < (unsigned)N_NODES) atomicAdd(&g_cnt[d4.w], 1);
    }
}

// ---------------- bucket offsets: block scan + atomic block base -------------
__global__ void offsets_kernel() {
    __shared__ int sh[1024];
    __shared__ int sbase;
    int tid = threadIdx.x;
    int gid = blockIdx.x * 1024 + tid;
    int v = 0;
    if (gid < N_NODES) {
        int c = g_cnt[gid];
        v = c;
        g_dinv[gid] = rsqrtf((float)(c + 1));   // +1 self-loop
    }
    sh[tid] = v;
    __syncthreads();
    for (int o = 1; o < 1024; o <<= 1) {
        int x = (tid >= o) ? sh[tid - o] : 0;
        __syncthreads();
        sh[tid] += x;
        __syncthreads();
    }
    if (tid == 1023) sbase = atomicAdd(&g_total, sh[1023]);
    __syncthreads();
    if (gid < N_NODES) {
        int start = sbase + sh[tid] - v;
        g_off[gid] = start;
        g_cur[gid] = start;
    }
}

// ---------------- CSR fill: src id only, 4 edges/thread ----------------------
__global__ void fill_kernel(const int* __restrict__ eidx) {
    int e0 = (blockIdx.x * blockDim.x + threadIdx.x) * 4;
    if (e0 < N_EDGES) {
        int4 s4 = *(const int4*)(eidx + e0);
        int4 d4 = *(const int4*)(eidx + N_EDGES + e0);
#pragma unroll
        for (int j = 0; j < 4; j++) {
            int s = (j == 0) ? s4.x : (j == 1) ? s4.y : (j == 2) ? s4.z : s4.w;
            int d = (j == 0) ? d4.x : (j == 1) ? d4.y : (j == 2) ? d4.z : d4.w;
            if ((unsigned)s < (unsigned)N_NODES && (unsigned)d < (unsigned)N_NODES) {
                int p = atomicAdd(&g_cur[d], 1);
                g_src[p] = s;
            }
        }
    }
}

// ---------------- dense GEMM: C[M x 64] = dinv[m] * (A[M x K] @ W[K x 64]) ---
// Tile 256 rows x 64 cols, K staged 16 at a time, register-staged prefetch.
// Inner loop uses packed fma.rn.f32x2: accumulators paired over rows, W
// duplicated in smem so (w,w) operand pairs come free from LDS.128.
template<int K, bool A_FROM_SCRATCH>
__global__ __launch_bounds__(256, 2)
void gemm_kernel(const float* __restrict__ Aext, const float* __restrict__ W) {
    __shared__ float sA[16][260];        // transposed: sA[k][m]
    __shared__ float sWd[16][136];       // duplicated: sWd[k][2c] = sWd[k][2c+1] = W[k][c]

    const float* __restrict__ A = A_FROM_SCRATCH ? (const float*)g_a : Aext;
    float* __restrict__ C = g_h;

    const int tid = threadIdx.x;
    const int m0  = blockIdx.x * 256;
    const int tr  = tid >> 3;            // 0..31 -> rows tr*8..tr*8+7
    const int tc  = tid & 7;             // 0..7  -> cols tc*4..+3 and +32..+35
    const int lr  = tid >> 2;
    const int lq  = tid & 3;
    const int wk  = tid >> 4;
    const int wc  = (tid & 15) << 2;

    // acc2[ip][j]: lanes = (row 2ip, row 2ip+1), column j (j<4: tc*4+j, j>=4: tc*4+28+j)
    unsigned long long acc2[4][8];
#pragma unroll
    for (int ip = 0; ip < 4; ip++)
#pragma unroll
        for (int j = 0; j < 8; j++) acc2[ip][j] = 0ull;

    float4 pa[4];
    float4 pw;

#pragma unroll
    for (int p = 0; p < 4; p++) {
        int m = m0 + p * 64 + lr;
        int msafe = (m < N_NODES) ? m : (N_NODES - 1);
        pa[p] = *(const float4*)(A + (size_t)msafe * K + lq * 4);
    }
    pw = *(const float4*)(W + (size_t)wk * 64 + wc);

    for (int k0 = 0; k0 < K; k0 += 16) {
#pragma unroll
        for (int p = 0; p < 4; p++) {
            int mm = p * 64 + lr;
            sA[lq * 4 + 0][mm] = pa[p].x;
            sA[lq * 4 + 1][mm] = pa[p].y;
            sA[lq * 4 + 2][mm] = pa[p].z;
            sA[lq * 4 + 3][mm] = pa[p].w;
        }
        // duplicated W stores: two float4s per thread
        *(float4*)&sWd[wk][wc * 2]     = make_float4(pw.x, pw.x, pw.y, pw.y);
        *(float4*)&sWd[wk][wc * 2 + 4] = make_float4(pw.z, pw.z, pw.w, pw.w);
        __syncthreads();

        if (k0 + 16 < K) {
#pragma unroll
            for (int p = 0; p < 4; p++) {
                int m = m0 + p * 64 + lr;
                int msafe = (m < N_NODES) ? m : (N_NODES - 1);
                pa[p] = *(const float4*)(A + (size_t)msafe * K + k0 + 16 + lq * 4);
            }
            pw = *(const float4*)(W + (size_t)(k0 + 16 + wk) * 64 + wc);
        }

#pragma unroll
        for (int k = 0; k < 16; k++) {
            // row pairs (a[2ip], a[2ip+1]) direct from contiguous smem
            ulonglong2 a01 = *(const ulonglong2*)&sA[k][tr * 8];
            ulonglong2 a23 = *(const ulonglong2*)&sA[k][tr * 8 + 4];
            // duplicated (w, w) pairs direct from smem
            ulonglong2 w01 = *(const ulonglong2*)&sWd[k][tc * 8];
            ulonglong2 w23 = *(const ulonglong2*)&sWd[k][tc * 8 + 4];
            ulonglong2 w45 = *(const ulonglong2*)&sWd[k][tc * 8 + 64];
            ulonglong2 w67 = *(const ulonglong2*)&sWd[k][tc * 8 + 68];
            unsigned long long A2[4] = {a01.x, a01.y, a23.x, a23.y};
            unsigned long long Wd[8] = {w01.x, w01.y, w23.x, w23.y,
                                        w45.x, w45.y, w67.x, w67.y};
#pragma unroll
            for (int ip = 0; ip < 4; ip++)
#pragma unroll
                for (int j = 0; j < 8; j++)
                    FMA2(acc2[ip][j], A2[ip], Wd[j]);
        }
        __syncthreads();
    }

    // epilogue: unpack row pairs, scale by dinv, vector stores
#pragma unroll
    for (int ip = 0; ip < 4; ip++) {
        float lo[8], hi[8];
#pragma unroll
        for (int j = 0; j < 8; j++) UNPACK2(lo[j], hi[j], acc2[ip][j]);
#pragma unroll
        for (int half = 0; half < 2; half++) {
            int m = m0 + tr * 8 + ip * 2 + half;
            if (m < N_NODES) {
                float s = g_dinv[m];
                const float* c = half ? hi : lo;
                float4 o0 = make_float4(s * c[0], s * c[1], s * c[2], s * c[3]);
                float4 o1 = make_float4(s * c[4], s * c[5], s * c[6], s * c[7]);
                *(float4*)(C + (size_t)m * 64 + tc * 4)      = o0;
                *(float4*)(C + (size_t)m * 64 + tc * 4 + 32) = o1;
            }
        }
    }
}

// ---------------- CSR aggregation ------------------------------------------
// out[v] = (opt relu)( dinv[v] * (h~[v] + sum_e h~[src_e]) + b )
template<bool RELU, bool OUT_SCRATCH>
__global__ __launch_bounds__(256)
void agg_kernel(const float* __restrict__ bias, float* __restrict__ outext) {
    const float* __restrict__ h = (const float*)g_h;
    float* __restrict__ out = OUT_SCRATCH ? (float*)g_a : outext;

    int warp = (blockIdx.x * blockDim.x + threadIdx.x) >> 5;
    int lane = threadIdx.x & 31;
    if (warp >= N_NODES) return;
    const int v = warp;

    float2 acc = ((const float2*)(h + (size_t)v * 64))[lane];  // self term

    int beg = g_off[v];
    int end = beg + g_cnt[v];
#pragma unroll 4
    for (int i = beg; i < end; i++) {
        int s = g_src[i];
        float2 m = ((const float2*)(h + (size_t)s * 64))[lane];
        acc.x += m.x;
        acc.y += m.y;
    }

    float di = g_dinv[v];
    float2 b = ((const float2*)bias)[lane];
    acc.x = di * acc.x + b.x;
    acc.y = di * acc.y + b.y;
    if (RELU) {
        acc.x = fmaxf(acc.x, 0.f);
        acc.y = fmaxf(acc.y, 0.f);
    }
    ((float2*)(out + (size_t)v * 64))[lane] = acc;
}

// ---------------- launch ----------------------------------------------------
extern "C" void kernel_launch(void* const* d_in, const int* in_sizes, int n_in,
                              void* d_out, int out_size) {
    const float* x    = (const float*)d_in[0];
    const int*   eidx = (const int*)d_in[1];     // int32 [2, N_EDGES]
    const float* W1   = (const float*)d_in[2];
    const float* b1   = (const float*)d_in[3];
    const float* W2   = (const float*)d_in[4];
    const float* b2   = (const float*)d_in[5];
    float*       out  = (float*)d_out;

    const int init_blocks  = (N_NODES / 4 + 255) / 256;      // 98
    const int edge4_blocks = (N_EDGES / 4 + 255) / 256;      // 1563
    const int scan_blocks  = (N_NODES + 1023) / 1024;        // 98
    const int gemm_blocks  = (N_NODES + 255) / 256;          // 391
    const int agg_blocks   = (N_NODES + 7) / 8;              // 8 warps/block

    // --- graph structure (once per launch, reused by both layers) ---
    init_kernel<<<init_blocks, 256>>>();
    hist_kernel<<<edge4_blocks, 256>>>(eidx);
    offsets_kernel<<<scan_blocks, 1024>>>();
    fill_kernel<<<edge4_blocks, 256>>>(eidx);

    // --- layer 1: g_h = dinv * (x @ W1) ; g_a = relu(agg + b1) ---
    gemm_kernel<IN_DIM, false><<<gemm_blocks, 256>>>(x, W1);
    agg_kernel<true, true><<<agg_blocks, 256>>>(b1, nullptr);

    // --- layer 2: g_h = dinv * (g_a @ W2) ; out = agg + b2 ---
    gemm_kernel<HID_DIM, true><<<gemm_blocks, 256>>>(nullptr, W2);
    agg_kernel<false, false><<<agg_blocks, 256>>>(b2, out);
}

// round 11
// speedup vs baseline: 1.3454x; 1.3454x over previous
#include <cuda_runtime.h>
#include <cuda_bf16.h>
#include <stdint.h>

#define N_NODES 100000
#define N_EDGES 1600000
#define IN_DIM  128
#define HID_DIM 64
#define OUT_DIM 64

#define GEMM_BLOCKS ((N_NODES + 255) / 256)       // 391
#define EDGE4_BLOCKS ((N_EDGES / 4 + 255) / 256)  // 1563

// ---------------- scratch (static device globals; no allocation) -------------
// All zero-initialized at module load; every launch restores them to zero
// (offsets re-zeroes g_cnt, hist resets g_total) so graph replays are identical.
__device__ __align__(16) float g_h[N_NODES * 64];   // GEMM output, pre-scaled by dinv (h~)
__device__ __align__(16) float g_a[N_NODES * 64];   // layer1 activations
__device__ __align__(16) int   g_cnt[N_NODES];      // hist counters (zeroed each launch)
__device__ __align__(16) int   g_len[N_NODES];      // in-degree snapshot for agg
__device__ __align__(16) int   g_cur[N_NODES];      // fill cursor (seeded to bucket start)
__device__ __align__(16) float g_dinv[N_NODES];     // rsqrt(deg+1)
__device__ __align__(16) int   g_off[N_NODES];      // bucket start (for agg)
__device__ __align__(16) int   g_src[N_EDGES];      // source id only
__device__ int g_total;                             // global bucket cursor

// ---------------- degree histogram (edge_index int32 [2, N_EDGES]) -----------
// Also resets g_total for this launch (kernel boundary orders it vs offsets).
__global__ void hist_kernel(const int* __restrict__ eidx) {
    if (blockIdx.x == 0 && threadIdx.x == 0) g_total = 0;
    int e0 = (blockIdx.x * blockDim.x + threadIdx.x) * 4;
    if (e0 < N_EDGES) {
        int4 d4 = *(const int4*)(eidx + N_EDGES + e0);
        if ((unsigned)d4.x < (unsigned)N_NODES) atomicAdd(&g_cnt[d4.x], 1);
        if ((unsigned)d4.y < (unsigned)N_NODES) atomicAdd(&g_cnt[d4.y], 1);
        if ((unsigned)d4.z < (unsigned)N_NODES) atomicAdd(&g_cnt[d4.z], 1);
        if ((unsigned)d4.w < (unsigned)N_NODES) atomicAdd(&g_cnt[d4.w], 1);
    }
}

// ---------------- bucket offsets: block scan + atomic block base -------------
// Reads g_cnt, snapshots to g_len, zeroes g_cnt for the next replay.
__global__ void offsets_kernel() {
    __shared__ int sh[1024];
    __shared__ int sbase;
    int tid = threadIdx.x;
    int gid = blockIdx.x * 1024 + tid;
    int v = 0;
    if (gid < N_NODES) {
        int c = g_cnt[gid];
        g_cnt[gid] = 0;                  // restore for next launch/replay
        g_len[gid] = c;
        v = c;
        g_dinv[gid] = rsqrtf((float)(c + 1));   // +1 self-loop
    }
    sh[tid] = v;
    __syncthreads();
    for (int o = 1; o < 1024; o <<= 1) {
        int x = (tid >= o) ? sh[tid - o] : 0;
        __syncthreads();
        sh[tid] += x;
        __syncthreads();
    }
    if (tid == 1023) sbase = atomicAdd(&g_total, sh[1023]);
    __syncthreads();
    if (gid < N_NODES) {
        int start = sbase + sh[tid] - v;
        g_off[gid] = start;
        g_cur[gid] = start;
    }
}

// ---------------- GEMM device body: C[m] = dinv[m] * (A[m][:] @ W) -----------
// Tile 256 rows x 64 cols, K staged 16 at a time, register-staged prefetch.
template<int K>
__device__ __forceinline__ void gemm_body(const float* __restrict__ A,
                                          const float* __restrict__ W,
                                          float* __restrict__ C,
                                          int blk) {
    __shared__ float sA[16][260];
    __shared__ float sW[16][68];

    const int tid = threadIdx.x;
    const int m0  = blk * 256;
    const int tr  = tid >> 3;
    const int tc  = tid & 7;
    const int lr  = tid >> 2;
    const int lq  = tid & 3;
    const int wk  = tid >> 4;
    const int wc  = (tid & 15) << 2;

    float acc[8][8];
#pragma unroll
    for (int i = 0; i < 8; i++)
#pragma unroll
        for (int j = 0; j < 8; j++) acc[i][j] = 0.f;

    float4 pa[4];
    float4 pw;

#pragma unroll
    for (int p = 0; p < 4; p++) {
        int m = m0 + p * 64 + lr;
        int msafe = (m < N_NODES) ? m : (N_NODES - 1);
        pa[p] = *(const float4*)(A + (size_t)msafe * K + lq * 4);
    }
    pw = *(const float4*)(W + (size_t)wk * 64 + wc);

    for (int k0 = 0; k0 < K; k0 += 16) {
#pragma unroll
        for (int p = 0; p < 4; p++) {
            int mm = p * 64 + lr;
            sA[lq * 4 + 0][mm] = pa[p].x;
            sA[lq * 4 + 1][mm] = pa[p].y;
            sA[lq * 4 + 2][mm] = pa[p].z;
            sA[lq * 4 + 3][mm] = pa[p].w;
        }
        *(float4*)&sW[wk][wc] = pw;
        __syncthreads();

        if (k0 + 16 < K) {
#pragma unroll
            for (int p = 0; p < 4; p++) {
                int m = m0 + p * 64 + lr;
                int msafe = (m < N_NODES) ? m : (N_NODES - 1);
                pa[p] = *(const float4*)(A + (size_t)msafe * K + k0 + 16 + lq * 4);
            }
            pw = *(const float4*)(W + (size_t)(k0 + 16 + wk) * 64 + wc);
        }

#pragma unroll
        for (int k = 0; k < 16; k++) {
            float4 a0 = *(const float4*)&sA[k][tr * 8];
            float4 a1 = *(const float4*)&sA[k][tr * 8 + 4];
            float4 w0 = *(const float4*)&sW[k][tc * 4];
            float4 w1 = *(const float4*)&sW[k][tc * 4 + 32];
            float a[8] = {a0.x, a0.y, a0.z, a0.w, a1.x, a1.y, a1.z, a1.w};
            float w[8] = {w0.x, w0.y, w0.z, w0.w, w1.x, w1.y, w1.z, w1.w};
#pragma unroll
            for (int i = 0; i < 8; i++)
#pragma unroll
                for (int j = 0; j < 8; j++)
                    acc[i][j] += a[i] * w[j];
        }
        __syncthreads();
    }

#pragma unroll
    for (int i = 0; i < 8; i++) {
        int m = m0 + tr * 8 + i;
        if (m < N_NODES) {
            float s = g_dinv[m];
            float4 o0 = make_float4(s * acc[i][0], s * acc[i][1], s * acc[i][2], s * acc[i][3]);
            float4 o1 = make_float4(s * acc[i][4], s * acc[i][5], s * acc[i][6], s * acc[i][7]);
            *(float4*)(C + (size_t)m * 64 + tc * 4)      = o0;
            *(float4*)(C + (size_t)m * 64 + tc * 4 + 32) = o1;
        }
    }
}

// ---------------- fill device body: src id only, 4 edges/thread --------------
__device__ __forceinline__ void fill_body(const int* __restrict__ eidx, int blk) {
    int e0 = (blk * 256 + threadIdx.x) * 4;
    if (e0 < N_EDGES) {
        int4 s4 = *(const int4*)(eidx + e0);
        int4 d4 = *(const int4*)(eidx + N_EDGES + e0);
#pragma unroll
        for (int j = 0; j < 4; j++) {
            int s = (j == 0) ? s4.x : (j == 1) ? s4.y : (j == 2) ? s4.z : s4.w;
            int d = (j == 0) ? d4.x : (j == 1) ? d4.y : (j == 2) ? d4.z : d4.w;
            if ((unsigned)s < (unsigned)N_NODES && (unsigned)d < (unsigned)N_NODES) {
                int p = atomicAdd(&g_cur[d], 1);
                g_src[p] = s;
            }
        }
    }
}

// ---------------- combined fill + gemm1 (independent work, one launch) -------
// Blocks [0, GEMM_BLOCKS) run gemm1 (x @ W1); the rest run the CSR fill.
// Overlaps the ~50us GEMM with the ~27us scatter on different SMs.
__global__ __launch_bounds__(256, 2)
void fill_gemm1_kernel(const int* __restrict__ eidx,
                       const float* __restrict__ x,
                       const float* __restrict__ W1) {
    if (blockIdx.x < GEMM_BLOCKS) {
        gemm_body<IN_DIM>(x, W1, g_h, blockIdx.x);
    } else {
        fill_body(eidx, blockIdx.x - GEMM_BLOCKS);
    }
}

// ---------------- standalone gemm2 ------------------------------------------
__global__ __launch_bounds__(256, 2)
void gemm2_kernel(const float* __restrict__ W2) {
    gemm_body<HID_DIM>((const float*)g_a, W2, g_h, blockIdx.x);
}

// ---------------- CSR aggregation ------------------------------------------
// out[v] = (opt relu)( dinv[v] * (h~[v] + sum_e h~[src_e]) + b )
template<bool RELU, bool OUT_SCRATCH>
__global__ __launch_bounds__(256)
void agg_kernel(const float* __restrict__ bias, float* __restrict__ outext) {
    const float* __restrict__ h = (const float*)g_h;
    float* __restrict__ out = OUT_SCRATCH ? (float*)g_a : outext;

    int warp = (blockIdx.x * blockDim.x + threadIdx.x) >> 5;
    int lane = threadIdx.x & 31;
    if (warp >= N_NODES) return;
    const int v = warp;

    float2 acc = ((const float2*)(h + (size_t)v * 64))[lane];  // self term

    int beg = g_off[v];
    int end = beg + g_len[v];
#pragma unroll 4
    for (int i = beg; i < end; i++) {
        int s = g_src[i];
        float2 m = ((const float2*)(h + (size_t)s * 64))[lane];
        acc.x += m.x;
        acc.y += m.y;
    }

    float di = g_dinv[v];
    float2 b = ((const float2*)bias)[lane];
    acc.x = di * acc.x + b.x;
    acc.y = di * acc.y + b.y;
    if (RELU) {
        acc.x = fmaxf(acc.x, 0.f);
        acc.y = fmaxf(acc.y, 0.f);
    }
    ((float2*)(out + (size_t)v * 64))[lane] = acc;
}

// ---------------- launch ----------------------------------------------------
extern "C" void kernel_launch(void* const* d_in, const int* in_sizes, int n_in,
                              void* d_out, int out_size) {
    const float* x    = (const float*)d_in[0];
    const int*   eidx = (const int*)d_in[1];     // int32 [2, N_EDGES]
    const float* W1   = (const float*)d_in[2];
    const float* b1   = (const float*)d_in[3];
    const float* W2   = (const float*)d_in[4];
    const float* b2   = (const float*)d_in[5];
    float*       out  = (float*)d_out;

    const int scan_blocks = (N_NODES + 1023) / 1024;        // 98
    const int agg_blocks  = (N_NODES + 7) / 8;              // 8 warps/block

    // build prefix (g_cnt zero from load / restored by previous launch)
    hist_kernel<<<EDGE4_BLOCKS, 256>>>(eidx);
    offsets_kernel<<<scan_blocks, 1024>>>();

    // fill + gemm1 overlapped in one launch
    fill_gemm1_kernel<<<GEMM_BLOCKS + EDGE4_BLOCKS, 256>>>(eidx, x, W1);

    // layer 1 aggregation: g_a = relu(dinv*(sum)+b1)
    agg_kernel<true, true><<<agg_blocks, 256>>>(b1, nullptr);

    // layer 2
    gemm2_kernel<<<GEMM_BLOCKS, 256>>>(W2);
    agg_kernel<false, false><<<agg_blocks, 256>>>(b2, out);
}

// round 12
// speedup vs baseline: 1.4056x; 1.0447x over previous
#include <cuda_runtime.h>
#include <cuda_bf16.h>
#include <stdint.h>

#define N_NODES 100000
#define N_EDGES 1600000
#define IN_DIM  128
#define HID_DIM 64
#define OUT_DIM 64

#define GEMM_BLOCKS ((N_NODES + 255) / 256)       // 391
#define EDGE4_BLOCKS ((N_EDGES / 4 + 255) / 256)  // 1563

// ---------------- scratch (static device globals; no allocation) -------------
// All zero-initialized at module load; every launch restores them to zero
// (offsets re-zeroes g_cnt, hist resets g_total) so graph replays are identical.
__device__ __align__(16) float g_h[N_NODES * 64];   // GEMM output, pre-scaled by dinv (h~)
__device__ __align__(16) float g_a[N_NODES * 64];   // layer1 activations
__device__ __align__(16) int   g_cnt[N_NODES];      // hist counters (zeroed each launch)
__device__ __align__(16) int   g_len[N_NODES];      // in-degree snapshot for agg
__device__ __align__(16) int   g_cur[N_NODES];      // fill cursor (seeded to bucket start)
__device__ __align__(16) float g_dinv[N_NODES];     // rsqrt(deg+1)
__device__ __align__(16) int   g_off[N_NODES];      // bucket start (for agg)
__device__ __align__(16) int   g_src[N_EDGES];      // source id only
__device__ int g_total;                             // global bucket cursor

// ---------------- degree histogram (edge_index int32 [2, N_EDGES]) -----------
__global__ void hist_kernel(const int* __restrict__ eidx) {
    if (blockIdx.x == 0 && threadIdx.x == 0) g_total = 0;
    int e0 = (blockIdx.x * blockDim.x + threadIdx.x) * 4;
    if (e0 < N_EDGES) {
        int4 d4 = *(const int4*)(eidx + N_EDGES + e0);
        if ((unsigned)d4.x < (unsigned)N_NODES) atomicAdd(&g_cnt[d4.x], 1);
        if ((unsigned)d4.y < (unsigned)N_NODES) atomicAdd(&g_cnt[d4.y], 1);
        if ((unsigned)d4.z < (unsigned)N_NODES) atomicAdd(&g_cnt[d4.z], 1);
        if ((unsigned)d4.w < (unsigned)N_NODES) atomicAdd(&g_cnt[d4.w], 1);
    }
}

// ---------------- bucket offsets: block scan + atomic block base -------------
__global__ void offsets_kernel() {
    __shared__ int sh[1024];
    __shared__ int sbase;
    int tid = threadIdx.x;
    int gid = blockIdx.x * 1024 + tid;
    int v = 0;
    if (gid < N_NODES) {
        int c = g_cnt[gid];
        g_cnt[gid] = 0;                  // restore for next launch/replay
        g_len[gid] = c;
        v = c;
        g_dinv[gid] = rsqrtf((float)(c + 1));   // +1 self-loop
    }
    sh[tid] = v;
    __syncthreads();
    for (int o = 1; o < 1024; o <<= 1) {
        int x = (tid >= o) ? sh[tid - o] : 0;
        __syncthreads();
        sh[tid] += x;
        __syncthreads();
    }
    if (tid == 1023) sbase = atomicAdd(&g_total, sh[1023]);
    __syncthreads();
    if (gid < N_NODES) {
        int start = sbase + sh[tid] - v;
        g_off[gid] = start;
        g_cur[gid] = start;
    }
}

// ---------------- GEMM device body: C[m] = dinv[m] * (A[m][:] @ W) -----------
template<int K>
__device__ __forceinline__ void gemm_body(const float* __restrict__ A,
                                          const float* __restrict__ W,
                                          float* __restrict__ C,
                                          int blk) {
    __shared__ float sA[16][260];
    __shared__ float sW[16][68];

    const int tid = threadIdx.x;
    const int m0  = blk * 256;
    const int tr  = tid >> 3;
    const int tc  = tid & 7;
    const int lr  = tid >> 2;
    const int lq  = tid & 3;
    const int wk  = tid >> 4;
    const int wc  = (tid & 15) << 2;

    float acc[8][8];
#pragma unroll
    for (int i = 0; i < 8; i++)
#pragma unroll
        for (int j = 0; j < 8; j++) acc[i][j] = 0.f;

    float4 pa[4];
    float4 pw;

#pragma unroll
    for (int p = 0; p < 4; p++) {
        int m = m0 + p * 64 + lr;
        int msafe = (m < N_NODES) ? m : (N_NODES - 1);
        pa[p] = *(const float4*)(A + (size_t)msafe * K + lq * 4);
    }
    pw = *(const float4*)(W + (size_t)wk * 64 + wc);

    for (int k0 = 0; k0 < K; k0 += 16) {
#pragma unroll
        for (int p = 0; p < 4; p++) {
            int mm = p * 64 + lr;
            sA[lq * 4 + 0][mm] = pa[p].x;
            sA[lq * 4 + 1][mm] = pa[p].y;
            sA[lq * 4 + 2][mm] = pa[p].z;
            sA[lq * 4 + 3][mm] = pa[p].w;
        }
        *(float4*)&sW[wk][wc] = pw;
        __syncthreads();

        if (k0 + 16 < K) {
#pragma unroll
            for (int p = 0; p < 4; p++) {
                int m = m0 + p * 64 + lr;
                int msafe = (m < N_NODES) ? m : (N_NODES - 1);
                pa[p] = *(const float4*)(A + (size_t)msafe * K + k0 + 16 + lq * 4);
            }
            pw = *(const float4*)(W + (size_t)(k0 + 16 + wk) * 64 + wc);
        }

#pragma unroll
        for (int k = 0; k < 16; k++) {
            float4 a0 = *(const float4*)&sA[k][tr * 8];
            float4 a1 = *(const float4*)&sA[k][tr * 8 + 4];
            float4 w0 = *(const float4*)&sW[k][tc * 4];
            float4 w1 = *(const float4*)&sW[k][tc * 4 + 32];
            float a[8] = {a0.x, a0.y, a0.z, a0.w, a1.x, a1.y, a1.z, a1.w};
            float w[8] = {w0.x, w0.y, w0.z, w0.w, w1.x, w1.y, w1.z, w1.w};
#pragma unroll
            for (int i = 0; i < 8; i++)
#pragma unroll
                for (int j = 0; j < 8; j++)
                    acc[i][j] += a[i] * w[j];
        }
        __syncthreads();
    }

#pragma unroll
    for (int i = 0; i < 8; i++) {
        int m = m0 + tr * 8 + i;
        if (m < N_NODES) {
            float s = g_dinv[m];
            float4 o0 = make_float4(s * acc[i][0], s * acc[i][1], s * acc[i][2], s * acc[i][3]);
            float4 o1 = make_float4(s * acc[i][4], s * acc[i][5], s * acc[i][6], s * acc[i][7]);
            *(float4*)(C + (size_t)m * 64 + tc * 4)      = o0;
            *(float4*)(C + (size_t)m * 64 + tc * 4 + 32) = o1;
        }
    }
}

// ---------------- fill device body: src id only, 4 edges/thread --------------
__device__ __forceinline__ void fill_body(const int* __restrict__ eidx, int blk) {
    int e0 = (blk * 256 + threadIdx.x) * 4;
    if (e0 < N_EDGES) {
        int4 s4 = *(const int4*)(eidx + e0);
        int4 d4 = *(const int4*)(eidx + N_EDGES + e0);
#pragma unroll
        for (int j = 0; j < 4; j++) {
            int s = (j == 0) ? s4.x : (j == 1) ? s4.y : (j == 2) ? s4.z : s4.w;
            int d = (j == 0) ? d4.x : (j == 1) ? d4.y : (j == 2) ? d4.z : d4.w;
            if ((unsigned)s < (unsigned)N_NODES && (unsigned)d < (unsigned)N_NODES) {
                int p = atomicAdd(&g_cur[d], 1);
                g_src[p] = s;
            }
        }
    }
}

// ---------------- combined fill + gemm1 (independent work, one launch) -------
__global__ __launch_bounds__(256, 2)
void fill_gemm1_kernel(const int* __restrict__ eidx,
                       const float* __restrict__ x,
                       const float* __restrict__ W1) {
    if (blockIdx.x < GEMM_BLOCKS) {
        gemm_body<IN_DIM>(x, W1, g_h, blockIdx.x);
    } else {
        fill_body(eidx, blockIdx.x - GEMM_BLOCKS);
    }
}

// ---------------- standalone gemm2 ------------------------------------------
__global__ __launch_bounds__(256, 2)
void gemm2_kernel(const float* __restrict__ W2) {
    gemm_body<HID_DIM>((const float*)g_a, W2, g_h, blockIdx.x);
}

// ---------------- CSR aggregation ------------------------------------------
// out[v] = (opt relu)( dinv[v] * (h~[v] + sum_e h~[src_e]) + b )
// One warp per node split into two half-warps: lanes 0-15 process even edges,
// lanes 16-31 odd edges; each lane holds float4 (16 lanes x 4 = 64 features).
// Two independent accumulator chains + LDG.128 gathers double per-warp MLP.
template<bool RELU, bool OUT_SCRATCH>
__global__ __launch_bounds__(256)
void agg_kernel(const float* __restrict__ bias, float* __restrict__ outext) {
    const float* __restrict__ h = (const float*)g_h;
    float* __restrict__ out = OUT_SCRATCH ? (float*)g_a : outext;

    int warp = (blockIdx.x * blockDim.x + threadIdx.x) >> 5;
    int lane = threadIdx.x & 31;
    if (warp >= N_NODES) return;
    const int v = warp;
    const int half = lane >> 4;          // 0: even edges + self, 1: odd edges
    const int fl   = (lane & 15) << 2;   // feature offset (0,4,...,60)

    float4 acc;
    if (half == 0) {
        acc = *(const float4*)(h + (size_t)v * 64 + fl);   // self term
    } else {
        acc = make_float4(0.f, 0.f, 0.f, 0.f);
    }

    int beg = g_off[v];
    int end = beg + g_len[v];
#pragma unroll 4
    for (int i = beg + half; i < end; i += 2) {
        int s = g_src[i];
        float4 m = *(const float4*)(h + (size_t)s * 64 + fl);
        acc.x += m.x;
        acc.y += m.y;
        acc.z += m.z;
        acc.w += m.w;
    }

    // merge the two half-warp partial sums
    acc.x += __shfl_xor_sync(0xFFFFFFFFu, acc.x, 16);
    acc.y += __shfl_xor_sync(0xFFFFFFFFu, acc.y, 16);
    acc.z += __shfl_xor_sync(0xFFFFFFFFu, acc.z, 16);
    acc.w += __shfl_xor_sync(0xFFFFFFFFu, acc.w, 16);

    if (half == 0) {
        float di = g_dinv[v];
        float4 b = *(const float4*)(bias + fl);
        acc.x = di * acc.x + b.x;
        acc.y = di * acc.y + b.y;
        acc.z = di * acc.z + b.z;
        acc.w = di * acc.w + b.w;
        if (RELU) {
            acc.x = fmaxf(acc.x, 0.f);
            acc.y = fmaxf(acc.y, 0.f);
            acc.z = fmaxf(acc.z, 0.f);
            acc.w = fmaxf(acc.w, 0.f);
        }
        *(float4*)(out + (size_t)v * 64 + fl) = acc;
    }
}

// ---------------- launch ----------------------------------------------------
extern "C" void kernel_launch(void* const* d_in, const int* in_sizes, int n_in,
                              void* d_out, int out_size) {
    const float* x    = (const float*)d_in[0];
    const int*   eidx = (const int*)d_in[1];     // int32 [2, N_EDGES]
    const float* W1   = (const float*)d_in[2];
    const float* b1   = (const float*)d_in[3];
    const float* W2   = (const float*)d_in[4];
    const float* b2   = (const float*)d_in[5];
    float*       out  = (float*)d_out;

    const int scan_blocks = (N_NODES + 1023) / 1024;        // 98
    const int agg_blocks  = (N_NODES + 7) / 8;              // 8 warps/block

    // build prefix (g_cnt zero from load / restored by previous launch)
    hist_kernel<<<EDGE4_BLOCKS, 256>>>(eidx);
    offsets_kernel<<<scan_blocks, 1024>>>();

    // fill + gemm1 overlapped in one launch
    fill_gemm1_kernel<<<GEMM_BLOCKS + EDGE4_BLOCKS, 256>>>(eidx, x, W1);

    // layer 1 aggregation: g_a = relu(dinv*(sum)+b1)
    agg_kernel<true, true><<<agg_blocks, 256>>>(b1, nullptr);

    // layer 2
    gemm2_kernel<<<GEMM_BLOCKS, 256>>>(W2);
    agg_kernel<false, false><<<agg_blocks, 256>>>(b2, out);
}